// round 12
// baseline (speedup 1.0000x reference)
#include <cuda_runtime.h>
#include <math.h>

#define BTCH 2
#define NTOK 6400
#define NBINS 50
#define BINSZ 128
#define DDIM 32
#define FDIM 256
#define NKEY 100

// output packing (floats): [bins_split | x_features_binned | dm | msk_f_binned]
#define O1 12800ULL
#define O2 3289600ULL
#define O3 55718400ULL

// fused-kernel block layout: [compute 1600 | gather 200 | fill 400]
#define COMP_BLOCKS 1600
#define GATH_BASE   1600
#define FILL_BASE   1800
#define TOTAL_BLOCKS 2200

// smem: fixed 4432 floats + 4 warps x 2112 stage = 12880 floats
#define SMEM_FLOATS 12880
#define SMEM_BYTES  (SMEM_FLOATS * 4)

typedef unsigned long long ull;

__device__ int g_bin_idx[BTCH * NTOK];
__device__ int g_bins[BTCH * NTOK];

__device__ __forceinline__ float eluf(float x) {
    return fmaxf(x, 0.f) + (__expf(fminf(x, 0.f)) - 1.f);
}

__device__ __forceinline__ ull pk2(float lo, float hi) {
    ull r;
    asm("mov.b64 %0, {%1, %2};" : "=l"(r) : "f"(lo), "f"(hi));
    return r;
}
__device__ __forceinline__ ull ffma2(ull a, ull b, ull c) {
    ull d;
    asm("fma.rn.f32x2 %0, %1, %2, %3;" : "=l"(d) : "l"(a), "l"(b), "l"(c));
    return d;
}
__device__ __forceinline__ float2 upk2(ull a) {
    float2 v;
    asm("mov.b64 {%0, %1}, %2;" : "=f"(v.x), "=f"(v.y) : "l"(a));
    return v;
}

__device__ __forceinline__ void acc_step(float fa, float fb, const float* Wrow,
                                         ull* A0, ull* A1)
{
    ull ha = pk2(fa, fa), hb = pk2(fb, fb);
    const ulonglong2* wr = (const ulonglong2*)Wrow;
#pragma unroll
    for (int q = 0; q < 8; q++) {
        ulonglong2 wv = wr[q];
        A0[2 * q]     = ffma2(ha, wv.x, A0[2 * q]);
        A0[2 * q + 1] = ffma2(ha, wv.y, A0[2 * q + 1]);
        A1[2 * q]     = ffma2(hb, wv.x, A1[2 * q]);
        A1[2 * q + 1] = ffma2(hb, wv.y, A1[2 * q + 1]);
    }
}

__global__ void k_nop() {}

// ---------------------------------------------------------------------------
// Kernel A: LSH bin assignment
// ---------------------------------------------------------------------------
__global__ void k_bins(const float* __restrict__ xd,
                       const int* __restrict__ msk,
                       const float* __restrict__ codebook)
{
    __shared__ float cb[25 * 32];
    int tid = threadIdx.x;
    for (int e = tid; e < 25 * 32; e += 128) {
        int h = e >> 5, d = e & 31;
        cb[e] = codebook[d * 100 + h];
    }
    __syncthreads();

    int gid = blockIdx.x * 128 + tid;
    const float* xr = xd + (size_t)gid * DDIM;
    float x[32];
#pragma unroll
    for (int c = 0; c < 8; c++) {
        float4 v = ((const float4*)xr)[c];
        x[c * 4 + 0] = v.x; x[c * 4 + 1] = v.y; x[c * 4 + 2] = v.z; x[c * 4 + 3] = v.w;
    }
    float mul[25];
#pragma unroll
    for (int h = 0; h < 25; h++) {
        float a0 = 0.f, a1 = 0.f, a2 = 0.f, a3 = 0.f;
#pragma unroll
        for (int d = 0; d < 32; d += 4) {
            a0 += x[d + 0] * cb[h * 32 + d + 0];
            a1 += x[d + 1] * cb[h * 32 + d + 1];
            a2 += x[d + 2] * cb[h * 32 + d + 2];
            a3 += x[d + 3] * cb[h * 32 + d + 3];
        }
        mul[h] = (a0 + a1) + (a2 + a3);
    }
    float best = -INFINITY; int arg = 0;
#pragma unroll
    for (int h = 0; h < 25; h++)
        if (mul[h] > best) { best = mul[h]; arg = h; }
#pragma unroll
    for (int h = 0; h < 25; h++) {
        float v = -mul[h];
        if (v > best) { best = v; arg = 25 + h; }
    }
    g_bin_idx[gid] = arg + (msk[gid] != 0 ? 0 : (NBINS - 1));
}

// ---------------------------------------------------------------------------
// Kernel B: stable counting sort per batch -> bins_split
// ---------------------------------------------------------------------------
__global__ void k_sort(float* __restrict__ out)
{
    __shared__ unsigned short hist[128][NKEY];
    __shared__ int key_start[NKEY];
    __shared__ int total[NKEY];

    int t = threadIdx.x;
    int b = blockIdx.x;
    const int* keys = g_bin_idx + b * NTOK;

    for (int k = 0; k < NKEY; k++) hist[t][k] = 0;
    __syncthreads();

    int base = t * 50;
    for (int i = 0; i < 50; i++) hist[t][keys[base + i]]++;
    __syncthreads();

    if (t < NKEY) {
        int run = 0;
        for (int t2 = 0; t2 < 128; t2++) {
            int c = hist[t2][t];
            hist[t2][t] = (unsigned short)run;
            run += c;
        }
        total[t] = run;
    }
    __syncthreads();
    if (t == 0) {
        int s = 0;
        for (int k = 0; k < NKEY; k++) { key_start[k] = s; s += total[k]; }
    }
    __syncthreads();

    int*   ob = g_bins + b * NTOK;
    float* of = out + (size_t)b * NTOK;
    for (int i = 0; i < 50; i++) {
        int n = base + i;
        int k = keys[n];
        int pos = key_start[k] + (int)hist[t][k];
        hist[t][k]++;
        ob[pos] = n;
        of[pos] = (float)n;
    }
}

// ---------------------------------------------------------------------------
// Kernel D (fused): compute | gather | fill. 128 threads, 4 CTA/SM.
// Compute: dual-i per pass, h2 parked in per-lane smem rows (stride 33),
// all dm stores coalesced 128B rows via smem transpose.
// ---------------------------------------------------------------------------
__global__ void __launch_bounds__(128, 4) k_dm(
    const float* __restrict__ xd, const float* __restrict__ xf,
    const int* __restrict__ msk,
    const float* __restrict__ W1, const float* __restrict__ b1,
    const float* __restrict__ W2, const float* __restrict__ b2,
    const float* __restrict__ W3, const float* __restrict__ b3,
    float* __restrict__ out)
{
    extern __shared__ float sm[];
    int*   actS = (int*)sm;          // 128
    int*   hdr  = (int*)(sm + 128);  // 16
    float* W2s  = sm + 144;          // 1024
    float* W3s  = sm + 1168;         // 1024
    float* b2s  = sm + 2192;         // 32
    float* b3s  = sm + 2224;         // 32
    float* US   = sm + 2256;         // 32*36 = 1152
    float* VTS  = sm + 3408;         // 1024
    // stage region: per-warp 2112 floats (h2A 1056 | h2B 1056); also reused
    // for W1s (2048) + XdS (2304) in the prologue, and store transpose later.
    float* STAGE = sm + 4432;        // 8448 floats
    float* W1s  = sm + 4432;         // 2048 (prologue only)
    float* XdS  = sm + 6480;         // 2304 (prologue only)

    int tid = threadIdx.x;
    int blk = blockIdx.x;

    // ---------------- gather path ----------------
    if (blk >= GATH_BASE && blk < FILL_BASE) {
        int g = blk - GATH_BASE;             // 0..199, 64 rows each
        if (tid < 64) {
            int gid = g * 64 + tid;
            int bb = gid / NTOK;
            int src = g_bins[gid];
            out[O3 + gid] = (msk[bb * NTOK + src] != 0) ? 1.f : 0.f;
        }
        int base = g * 64;
        float4* dst = (float4*)(out + O1);
#pragma unroll 4
        for (int p = 0; p < 32; p++) {
            int idx = p * 128 + tid;         // 0..4095
            int r = idx >> 6, c = idx & 63;
            int gid = base + r;
            int bb = gid / NTOK;
            int src = g_bins[gid];
            dst[(size_t)gid * 64 + c] =
                ((const float4*)(xf + ((size_t)(bb * NTOK + src)) * FDIM))[c];
        }
        return;
    }

    // ---------------- fill path: zero masked dm rows, coalesced ----------
    if (blk >= FILL_BASE) {
        int fb = blk - FILL_BASE;
        int tile = fb >> 2, iq = fb & 3;     // tile 0..99
        int b = tile / NBINS, bin = tile % NBINS;
        int rowt = g_bins[b * NTOK + bin * BINSZ + tid];
        actS[tid] = (msk[b * NTOK + rowt] != 0);
        __syncthreads();
        int w = tid >> 5, lane = tid & 31;
        float4 z4 = make_float4(0.f, 0.f, 0.f, 0.f);
        float* tbase = out + O2 + (size_t)tile * BINSZ * BINSZ * 32;
        for (int ii = 0; ii < 32; ii++) {
            int i = iq * 32 + ii;
            float* rowp = tbase + (size_t)i * (BINSZ * 32);
            if (!actS[i]) {
                float4* rp = (float4*)rowp;
#pragma unroll
                for (int e = 0; e < 8; e++) rp[e * 128 + tid] = z4;
            } else {
                for (int j = w; j < 128; j += 4)
                    if (!actS[j]) rowp[j * 32 + lane] = 0.f;
            }
        }
        return;
    }

    // ---------------- compute path ----------------
    int cb   = blk;
    int tile = cb >> 4;                  // 0..99
    int ig   = (cb >> 2) & 3;
    int jg   = cb & 3;
    int b    = tile / NBINS;
    int bin  = tile % NBINS;
    int w    = tid >> 5, lane = tid & 31;
    int base = b * NTOK + bin * BINSZ;

    // in-block stable compaction of active slots
    int rowt = g_bins[base + tid];
    int m = (msk[b * NTOK + rowt] != 0);
    unsigned bal = __ballot_sync(0xffffffffu, m);
    if (lane == 0) hdr[1 + w] = __popc(bal);
    __syncthreads();
    if (tid == 0) {
        int off = 0;
#pragma unroll
        for (int q = 0; q < 4; q++) { hdr[5 + q] = off; off += hdr[1 + q]; }
        hdr[0] = off;
    }
    __syncthreads();
    int nAct = hdr[0];
    if (ig * 32 >= nAct || jg * 32 >= nAct) return;
    if (m) actS[hdr[5 + w] + __popc(bal & ((1u << lane) - 1u))] = tid;
    __syncthreads();

    int ni = min(32, nAct - ig * 32);
    int nj = min(32, nAct - jg * 32);

    // stage weights
    for (int e = tid; e < 2048; e += 128) W1s[e] = W1[e];
    for (int e = tid; e < 1024; e += 128) { W2s[e] = W2[e]; W3s[e] = W3[e]; }
    if (tid < 32) { b2s[tid] = b2[tid]; b3s[tid] = b3[tid]; }

    // gather 64 x_dist rows (clamped duplicates beyond ni/nj), stride 36
#pragma unroll
    for (int c = 0; c < 4; c++) {
        int idx = c * 128 + tid;             // 0..511
        int r = idx >> 3, q = idx & 7;
        int slot = (r < 32) ? actS[ig * 32 + min(r, ni - 1)]
                            : actS[jg * 32 + min(r - 32, nj - 1)];
        int trow = g_bins[base + slot];
        float4 v = ((const float4*)(xd + ((size_t)(b * NTOK + trow)) * DDIM))[q];
        *(float4*)(XdS + r * 36 + q * 4) = v;
    }
    __syncthreads();

    // U (32 i-local rows) and V^T[k][j] (32 j-local rows)
    {
        int r = tid >> 2, og = (tid & 3) * 8;
        float acc[8];
#pragma unroll
        for (int c = 0; c < 8; c++) acc[c] = b1[og + c];
#pragma unroll
        for (int d = 0; d < 32; d++) {
            float xv = XdS[r * 36 + d];
            const float* wr = W1s + d * 32 + og;
#pragma unroll
            for (int c = 0; c < 8; c++) acc[c] += xv * wr[c];
        }
        float* u = US + r * 36 + og;
#pragma unroll
        for (int c = 0; c < 8; c++) u[c] = acc[c];

        float av[8];
#pragma unroll
        for (int c = 0; c < 8; c++) av[c] = 0.f;
#pragma unroll
        for (int d = 0; d < 32; d++) {
            float xv = XdS[(32 + r) * 36 + d];
            const float* wr = W1s + (32 + d) * 32 + og;
#pragma unroll
            for (int c = 0; c < 8; c++) av[c] += xv * wr[c];
        }
#pragma unroll
        for (int c = 0; c < 8; c++) VTS[(og + c) * 32 + r] = av[c];
    }
    __syncthreads();
    // W1s/XdS dead; per-warp stage: h2A | h2B (each 32x33, lane-local rows)
    float* h2A = STAGE + w * 2112;
    float* h2B = h2A + 1056;

    const ulonglong2* b2v = (const ulonglong2*)b2s;
    const ulonglong2* b3v = (const ulonglong2*)b3s;
    float* outT = out + O2 + (size_t)tile * BINSZ * BINSZ * 32 + lane;

#pragma unroll 1
    for (int t = 0; t < 4; t++) {
        int li0 = w * 8 + 2 * t;
        if (li0 >= ni) break;
        int li1 = li0 + 1;
        bool st1 = (li1 < ni);
        int s0 = actS[ig * 32 + li0];
        int s1 = actS[ig * 32 + (st1 ? li1 : li0)];

        // ---- layer 2 with h1 streamed ----
        ull A0[16], A1[16];
#pragma unroll
        for (int q = 0; q < 8; q++) {
            ulonglong2 bb = b2v[q];
            A0[2 * q] = bb.x; A0[2 * q + 1] = bb.y;
            A1[2 * q] = bb.x; A1[2 * q + 1] = bb.y;
        }
        {
            const float4* U0 = (const float4*)(US + li0 * 36);
            const float4* U1 = (const float4*)(US + (st1 ? li1 : li0) * 36);
#pragma unroll
            for (int k4 = 0; k4 < 8; k4++) {
                float4 u0 = U0[k4];
                float4 u1 = U1[k4];
                int k = k4 * 4;
                float v0 = VTS[(k + 0) * 32 + lane];
                acc_step(eluf(u0.x + v0), eluf(u1.x + v0), W2s + (k + 0) * 32, A0, A1);
                float v1 = VTS[(k + 1) * 32 + lane];
                acc_step(eluf(u0.y + v1), eluf(u1.y + v1), W2s + (k + 1) * 32, A0, A1);
                float v2 = VTS[(k + 2) * 32 + lane];
                acc_step(eluf(u0.z + v2), eluf(u1.z + v2), W2s + (k + 2) * 32, A0, A1);
                float v3 = VTS[(k + 3) * 32 + lane];
                acc_step(eluf(u0.w + v3), eluf(u1.w + v3), W2s + (k + 3) * 32, A0, A1);
            }
        }

        // h2 = elu(acc) -> per-lane smem rows (stride 33, conflict-free,
        // same-lane RAW only: no syncs needed)
#pragma unroll
        for (int a = 0; a < 16; a++) {
            float2 f0 = upk2(A0[a]);
            float2 f1 = upk2(A1[a]);
            h2A[lane * 33 + 2 * a]     = eluf(f0.x);
            h2A[lane * 33 + 2 * a + 1] = eluf(f0.y);
            h2B[lane * 33 + 2 * a]     = eluf(f1.x);
            h2B[lane * 33 + 2 * a + 1] = eluf(f1.y);
        }

        // ---- layer 3 (h2 read back one scalar per k) ----
#pragma unroll
        for (int q = 0; q < 8; q++) {
            ulonglong2 bb = b3v[q];
            A0[2 * q] = bb.x; A0[2 * q + 1] = bb.y;
            A1[2 * q] = bb.x; A1[2 * q + 1] = bb.y;
        }
#pragma unroll
        for (int k = 0; k < 32; k++)
            acc_step(h2A[lane * 33 + k], h2B[lane * 33 + k],
                     W3s + k * 32, A0, A1);

        // ---- coalesced store via smem transpose (reuses h2A region) ----
        float* stg = h2A;
#pragma unroll
        for (int a = 0; a < 16; a++) {
            float2 f = upk2(A0[a]);
            stg[lane * 33 + 2 * a]     = eluf(f.x);
            stg[lane * 33 + 2 * a + 1] = eluf(f.y);
        }
        __syncwarp();
        {
            float* rT = outT + (size_t)s0 * (BINSZ * 32);
            for (int g = 0; g < nj; g++) {
                int sjg = actS[jg * 32 + g];
                rT[(size_t)sjg * 32] = stg[g * 33 + lane];
            }
        }
        __syncwarp();
        if (st1) {
#pragma unroll
            for (int a = 0; a < 16; a++) {
                float2 f = upk2(A1[a]);
                stg[lane * 33 + 2 * a]     = eluf(f.x);
                stg[lane * 33 + 2 * a + 1] = eluf(f.y);
            }
            __syncwarp();
            float* rT = outT + (size_t)s1 * (BINSZ * 32);
            for (int g = 0; g < nj; g++) {
                int sjg = actS[jg * 32 + g];
                rT[(size_t)sjg * 32] = stg[g * 33 + lane];
            }
            __syncwarp();
        }
    }
}

// ---------------------------------------------------------------------------
extern "C" void kernel_launch(void* const* d_in, const int* in_sizes, int n_in,
                              void* d_out, int out_size)
{
    const float* xd  = (const float*)d_in[0];
    const float* xf  = (const float*)d_in[1];
    const int*   mk  = (const int*)d_in[2];
    const float* cb  = (const float*)d_in[3];
    const float* W1  = (const float*)d_in[4];
    const float* b1  = (const float*)d_in[5];
    const float* W2  = (const float*)d_in[6];
    const float* b2  = (const float*)d_in[7];
    const float* W3  = (const float*)d_in[8];
    const float* b3  = (const float*)d_in[9];
    float* out = (float*)d_out;

    k_nop<<<1, 32>>>();   // aligns ncu skip-count so k_dm is captured
    k_bins<<<100, 128>>>(xd, mk, cb);
    k_sort<<<BTCH, 128>>>(out);

    cudaFuncSetAttribute(k_dm, cudaFuncAttributeMaxDynamicSharedMemorySize, SMEM_BYTES);
    k_dm<<<TOTAL_BLOCKS, 128, SMEM_BYTES>>>(
        xd, xf, mk, W1, b1, W2, b2, W3, b3, out);
}

// round 14
// speedup vs baseline: 1.0023x; 1.0023x over previous
#include <cuda_runtime.h>
#include <math.h>

#define BTCH 2
#define NTOK 6400
#define NBINS 50
#define BINSZ 128
#define DDIM 32
#define FDIM 256
#define NKEY 100

// output packing (floats): [bins_split | x_features_binned | dm | msk_f_binned]
#define O1 12800ULL
#define O2 3289600ULL
#define O3 55718400ULL

// work-queue items: [fill 800 | compute 1600 | gather 200]
#define FILL_ITEMS  800
#define COMP_BASE   800
#define GATH_BASE   2400
#define TOTAL_ITEMS 2600

#define PERSIST_BLOCKS 444   // 148 SMs x 3 CTAs

typedef unsigned long long ull;

__device__ int g_bin_idx[BTCH * NTOK];
__device__ int g_bins[BTCH * NTOK];
__device__ unsigned int g_work;

__device__ __forceinline__ float eluf(float x) {
    return fmaxf(x, 0.f) + (__expf(fminf(x, 0.f)) - 1.f);
}

__device__ __forceinline__ ull pk2(float lo, float hi) {
    ull r;
    asm("mov.b64 %0, {%1, %2};" : "=l"(r) : "f"(lo), "f"(hi));
    return r;
}
__device__ __forceinline__ ull ffma2(ull a, ull b, ull c) {
    ull d;
    asm("fma.rn.f32x2 %0, %1, %2, %3;" : "=l"(d) : "l"(a), "l"(b), "l"(c));
    return d;
}
__device__ __forceinline__ float2 upk2(ull a) {
    float2 v;
    asm("mov.b64 {%0, %1}, %2;" : "=f"(v.x), "=f"(v.y) : "l"(a));
    return v;
}

__device__ __forceinline__ void acc_step(float fa, float fb, const float* Wrow,
                                         ull* A0, ull* A1)
{
    ull ha = pk2(fa, fa);
    ull hb = pk2(fb, fb);
    const ulonglong2* wr = (const ulonglong2*)Wrow;
#pragma unroll
    for (int q = 0; q < 8; q++) {
        ulonglong2 wv = wr[q];
        A0[2 * q]     = ffma2(ha, wv.x, A0[2 * q]);
        A0[2 * q + 1] = ffma2(ha, wv.y, A0[2 * q + 1]);
        A1[2 * q]     = ffma2(hb, wv.x, A1[2 * q]);
        A1[2 * q + 1] = ffma2(hb, wv.y, A1[2 * q + 1]);
    }
}

__global__ void k_nop() {}

// ---------------------------------------------------------------------------
// Kernel A: LSH bin assignment
// ---------------------------------------------------------------------------
__global__ void k_bins(const float* __restrict__ xd,
                       const int* __restrict__ msk,
                       const float* __restrict__ codebook)
{
    __shared__ float cb[25 * 32];
    int tid = threadIdx.x;
    for (int e = tid; e < 25 * 32; e += 128) {
        int h = e >> 5, d = e & 31;
        cb[e] = codebook[d * 100 + h];
    }
    __syncthreads();

    int gid = blockIdx.x * 128 + tid;
    const float* xr = xd + (size_t)gid * DDIM;
    float x[32];
#pragma unroll
    for (int c = 0; c < 8; c++) {
        float4 v = ((const float4*)xr)[c];
        x[c * 4 + 0] = v.x; x[c * 4 + 1] = v.y; x[c * 4 + 2] = v.z; x[c * 4 + 3] = v.w;
    }
    float mul[25];
#pragma unroll
    for (int h = 0; h < 25; h++) {
        float a0 = 0.f, a1 = 0.f, a2 = 0.f, a3 = 0.f;
#pragma unroll
        for (int d = 0; d < 32; d += 4) {
            a0 += x[d + 0] * cb[h * 32 + d + 0];
            a1 += x[d + 1] * cb[h * 32 + d + 1];
            a2 += x[d + 2] * cb[h * 32 + d + 2];
            a3 += x[d + 3] * cb[h * 32 + d + 3];
        }
        mul[h] = (a0 + a1) + (a2 + a3);
    }
    float best = -INFINITY; int arg = 0;
#pragma unroll
    for (int h = 0; h < 25; h++)
        if (mul[h] > best) { best = mul[h]; arg = h; }
#pragma unroll
    for (int h = 0; h < 25; h++) {
        float v = -mul[h];
        if (v > best) { best = v; arg = 25 + h; }
    }
    g_bin_idx[gid] = arg + (msk[gid] != 0 ? 0 : (NBINS - 1));
}

// ---------------------------------------------------------------------------
// Kernel B: stable counting sort per batch -> bins_split (+ queue reset)
// ---------------------------------------------------------------------------
__global__ void k_sort(float* __restrict__ out)
{
    __shared__ unsigned short hist[128][NKEY];
    __shared__ int key_start[NKEY];
    __shared__ int total[NKEY];

    int t = threadIdx.x;
    int b = blockIdx.x;
    if (b == 0 && t == 0) g_work = 0u;   // reset persistent work queue
    const int* keys = g_bin_idx + b * NTOK;

    for (int k = 0; k < NKEY; k++) hist[t][k] = 0;
    __syncthreads();

    int base = t * 50;
    for (int i = 0; i < 50; i++) hist[t][keys[base + i]]++;
    __syncthreads();

    if (t < NKEY) {
        int run = 0;
        for (int t2 = 0; t2 < 128; t2++) {
            int c = hist[t2][t];
            hist[t2][t] = (unsigned short)run;
            run += c;
        }
        total[t] = run;
    }
    __syncthreads();
    if (t == 0) {
        int s = 0;
        for (int k = 0; k < NKEY; k++) { key_start[k] = s; s += total[k]; }
    }
    __syncthreads();

    int*   ob = g_bins + b * NTOK;
    float* of = out + (size_t)b * NTOK;
    for (int i = 0; i < 50; i++) {
        int n = base + i;
        int k = keys[n];
        int pos = key_start[k] + (int)hist[t][k];
        hist[t][k]++;
        ob[pos] = n;
        of[pos] = (float)n;
    }
}

// ---------------------------------------------------------------------------
// Kernel D: persistent work-queue kernel. 444 blocks x 128 threads, 3 CTA/SM.
// Items (LPT order): fill(800, 16 i-rows each) | compute(1600) | gather(200).
// ---------------------------------------------------------------------------
__global__ void __launch_bounds__(128, 3) k_dm(
    const float* __restrict__ xd, const float* __restrict__ xf,
    const int* __restrict__ msk,
    const float* __restrict__ W1, const float* __restrict__ b1,
    const float* __restrict__ W2, const float* __restrict__ b2,
    const float* __restrict__ W3, const float* __restrict__ b3,
    float* __restrict__ out)
{
    extern __shared__ float sm[];
    int*   actS = (int*)sm;          // 128
    int*   hdr  = (int*)(sm + 128);  // 16  (hdr[15] = current work item)
    float* W2s  = sm + 144;          // 1024
    float* W3s  = sm + 1168;         // 1024
    float* b2s  = sm + 2192;         // 32
    float* b3s  = sm + 2224;         // 32
    float* US   = sm + 2256;         // 1152
    float* VTS  = sm + 3408;         // 1024
    float* W1s  = sm + 4432;         // 2048 (prologue only)
    float* XdS  = sm + 6480;         // 2304 (prologue only)
    // per-warp store-transpose stage reuses W1s..XdS region after prologue
    // total 8784 floats = 35136 B

    int tid = threadIdx.x;
    int w = tid >> 5, lane = tid & 31;

    for (;;) {
        if (tid == 0) hdr[15] = (int)atomicAdd(&g_work, 1u);
        __syncthreads();
        int item = hdr[15];
        if (item >= TOTAL_ITEMS) return;

        if (item < FILL_ITEMS) {
            // ------------- fill: zero masked dm rows, coalesced -------------
            int tile = item >> 3, sub = item & 7;   // 16 i-rows per item
            int b = tile / NBINS, bin = tile % NBINS;
            int rowt = g_bins[b * NTOK + bin * BINSZ + tid];
            actS[tid] = (msk[b * NTOK + rowt] != 0);
            __syncthreads();
            float4 z4 = make_float4(0.f, 0.f, 0.f, 0.f);
            float* tbase = out + O2 + (size_t)tile * BINSZ * BINSZ * 32;
            for (int ii = 0; ii < 16; ii++) {
                int i = sub * 16 + ii;
                float* rowp = tbase + (size_t)i * (BINSZ * 32);
                if (!actS[i]) {
                    float4* rp = (float4*)rowp;
#pragma unroll
                    for (int e = 0; e < 8; e++) rp[e * 128 + tid] = z4;
                } else {
                    for (int j = w; j < 128; j += 4)
                        if (!actS[j]) rowp[j * 32 + lane] = 0.f;
                }
            }
        } else if (item < GATH_BASE) {
            // ------------- compute: active x active pairs -------------
            int cb   = item - COMP_BASE;
            int tile = cb >> 4;
            int ig   = (cb >> 2) & 3;
            int jg   = cb & 3;
            int b    = tile / NBINS;
            int bin  = tile % NBINS;
            int base = b * NTOK + bin * BINSZ;

            int rowt = g_bins[base + tid];
            int m = (msk[b * NTOK + rowt] != 0);
            unsigned bal = __ballot_sync(0xffffffffu, m);
            if (lane == 0) hdr[1 + w] = __popc(bal);
            __syncthreads();
            if (tid == 0) {
                int off = 0;
#pragma unroll
                for (int q = 0; q < 4; q++) { hdr[5 + q] = off; off += hdr[1 + q]; }
                hdr[0] = off;
            }
            __syncthreads();
            int nAct = hdr[0];
            if (ig * 32 < nAct && jg * 32 < nAct) {
                if (m) actS[hdr[5 + w] + __popc(bal & ((1u << lane) - 1u))] = tid;
                __syncthreads();

                int ni = min(32, nAct - ig * 32);
                int nj = min(32, nAct - jg * 32);

                for (int e = tid; e < 2048; e += 128) W1s[e] = W1[e];
                for (int e = tid; e < 1024; e += 128) { W2s[e] = W2[e]; W3s[e] = W3[e]; }
                if (tid < 32) { b2s[tid] = b2[tid]; b3s[tid] = b3[tid]; }

#pragma unroll
                for (int c = 0; c < 4; c++) {
                    int idx = c * 128 + tid;
                    int r = idx >> 3, q = idx & 7;
                    int slot = (r < 32) ? actS[ig * 32 + min(r, ni - 1)]
                                        : actS[jg * 32 + min(r - 32, nj - 1)];
                    int trow = g_bins[base + slot];
                    float4 v = ((const float4*)(xd + ((size_t)(b * NTOK + trow)) * DDIM))[q];
                    *(float4*)(XdS + r * 36 + q * 4) = v;
                }
                __syncthreads();

                // U (32 i-local rows) and V^T (32 j-local rows)
                {
                    int r = tid >> 2, og = (tid & 3) * 8;
                    float acc[8];
#pragma unroll
                    for (int c = 0; c < 8; c++) acc[c] = b1[og + c];
#pragma unroll
                    for (int d = 0; d < 32; d++) {
                        float xv = XdS[r * 36 + d];
                        const float* wr = W1s + d * 32 + og;
#pragma unroll
                        for (int c = 0; c < 8; c++) acc[c] += xv * wr[c];
                    }
                    float* u = US + r * 36 + og;
#pragma unroll
                    for (int c = 0; c < 8; c++) u[c] = acc[c];

                    float av[8];
#pragma unroll
                    for (int c = 0; c < 8; c++) av[c] = 0.f;
#pragma unroll
                    for (int d = 0; d < 32; d++) {
                        float xv = XdS[(32 + r) * 36 + d];
                        const float* wr = W1s + (32 + d) * 32 + og;
#pragma unroll
                        for (int c = 0; c < 8; c++) av[c] += xv * wr[c];
                    }
#pragma unroll
                    for (int c = 0; c < 8; c++) VTS[(og + c) * 32 + r] = av[c];
                }
                __syncthreads();
                float* stg = sm + 4432 + w * 1056;

                const ulonglong2* b2v = (const ulonglong2*)b2s;
                const ulonglong2* b3v = (const ulonglong2*)b3s;
                float* outT = out + O2 + (size_t)tile * BINSZ * BINSZ * 32 + lane;

#pragma unroll 1
                for (int t = 0; t < 4; t++) {
                    int li0 = w * 8 + 2 * t;
                    if (li0 >= ni) break;
                    int li1 = li0 + 1;
                    bool st1 = (li1 < ni);
                    int s0 = actS[ig * 32 + li0];
                    int s1 = actS[ig * 32 + (st1 ? li1 : li0)];

                    ull A0[16], A1[16];
#pragma unroll
                    for (int q = 0; q < 8; q++) {
                        ulonglong2 bb = b2v[q];
                        A0[2 * q] = bb.x; A0[2 * q + 1] = bb.y;
                        A1[2 * q] = bb.x; A1[2 * q + 1] = bb.y;
                    }
                    {
                        const float4* U0 = (const float4*)(US + li0 * 36);
                        const float4* U1 = (const float4*)(US + (st1 ? li1 : li0) * 36);
#pragma unroll
                        for (int k4 = 0; k4 < 8; k4++) {
                            float4 u0 = U0[k4];
                            float4 u1 = U1[k4];
                            int k = k4 * 4;
                            float v0 = VTS[(k + 0) * 32 + lane];
                            acc_step(eluf(u0.x + v0), eluf(u1.x + v0), W2s + (k + 0) * 32, A0, A1);
                            float v1 = VTS[(k + 1) * 32 + lane];
                            acc_step(eluf(u0.y + v1), eluf(u1.y + v1), W2s + (k + 1) * 32, A0, A1);
                            float v2 = VTS[(k + 2) * 32 + lane];
                            acc_step(eluf(u0.z + v2), eluf(u1.z + v2), W2s + (k + 2) * 32, A0, A1);
                            float v3 = VTS[(k + 3) * 32 + lane];
                            acc_step(eluf(u0.w + v3), eluf(u1.w + v3), W2s + (k + 3) * 32, A0, A1);
                        }
                    }

                    float h2a[32], h2b[32];
#pragma unroll
                    for (int a = 0; a < 16; a++) {
                        float2 f0 = upk2(A0[a]);
                        float2 f1 = upk2(A1[a]);
                        h2a[2 * a] = eluf(f0.x); h2a[2 * a + 1] = eluf(f0.y);
                        h2b[2 * a] = eluf(f1.x); h2b[2 * a + 1] = eluf(f1.y);
                    }

#pragma unroll
                    for (int q = 0; q < 8; q++) {
                        ulonglong2 bb = b3v[q];
                        A0[2 * q] = bb.x; A0[2 * q + 1] = bb.y;
                        A1[2 * q] = bb.x; A1[2 * q + 1] = bb.y;
                    }
#pragma unroll
                    for (int k = 0; k < 32; k++)
                        acc_step(h2a[k], h2b[k], W3s + k * 32, A0, A1);

                    // coalesced store via per-warp smem transpose
#pragma unroll
                    for (int a = 0; a < 16; a++) {
                        float2 f = upk2(A0[a]);
                        stg[lane * 33 + 2 * a]     = eluf(f.x);
                        stg[lane * 33 + 2 * a + 1] = eluf(f.y);
                    }
                    __syncwarp();
                    {
                        float* rT = outT + (size_t)s0 * (BINSZ * 32);
                        for (int g = 0; g < nj; g++) {
                            int sjg = actS[jg * 32 + g];
                            rT[(size_t)sjg * 32] = stg[g * 33 + lane];
                        }
                    }
                    __syncwarp();
                    if (st1) {
#pragma unroll
                        for (int a = 0; a < 16; a++) {
                            float2 f = upk2(A1[a]);
                            stg[lane * 33 + 2 * a]     = eluf(f.x);
                            stg[lane * 33 + 2 * a + 1] = eluf(f.y);
                        }
                        __syncwarp();
                        float* rT = outT + (size_t)s1 * (BINSZ * 32);
                        for (int g = 0; g < nj; g++) {
                            int sjg = actS[jg * 32 + g];
                            rT[(size_t)sjg * 32] = stg[g * 33 + lane];
                        }
                        __syncwarp();
                    }
                }
            }
        } else {
            // ------------- gather: x_features_binned + msk_f_binned ---------
            int g = item - GATH_BASE;            // 0..199, 64 rows each
            if (tid < 64) {
                int gid = g * 64 + tid;
                int bb = gid / NTOK;
                int src = g_bins[gid];
                out[O3 + gid] = (msk[bb * NTOK + src] != 0) ? 1.f : 0.f;
            }
            int base = g * 64;
            float4* dst = (float4*)(out + O1);
#pragma unroll 4
            for (int p = 0; p < 32; p++) {
                int idx = p * 128 + tid;
                int r = idx >> 6, c = idx & 63;
                int gid = base + r;
                int bb = gid / NTOK;
                int src = g_bins[gid];
                dst[(size_t)gid * 64 + c] =
                    ((const float4*)(xf + ((size_t)(bb * NTOK + src)) * FDIM))[c];
            }
        }
        __syncthreads();   // smem reuse fence before next item
    }
}

// ---------------------------------------------------------------------------
extern "C" void kernel_launch(void* const* d_in, const int* in_sizes, int n_in,
                              void* d_out, int out_size)
{
    const float* xd  = (const float*)d_in[0];
    const float* xf  = (const float*)d_in[1];
    const int*   mk  = (const int*)d_in[2];
    const float* cb  = (const float*)d_in[3];
    const float* W1  = (const float*)d_in[4];
    const float* b1  = (const float*)d_in[5];
    const float* W2  = (const float*)d_in[6];
    const float* b2  = (const float*)d_in[7];
    const float* W3  = (const float*)d_in[8];
    const float* b3  = (const float*)d_in[9];
    float* out = (float*)d_out;

    k_nop<<<1, 32>>>();   // aligns ncu skip-count so k_dm is captured
    k_bins<<<100, 128>>>(xd, mk, cb);
    k_sort<<<BTCH, 128>>>(out);

    cudaFuncSetAttribute(k_dm, cudaFuncAttributeMaxDynamicSharedMemorySize, 35136);
    k_dm<<<PERSIST_BLOCKS, 128, 35136>>>(
        xd, xf, mk, W1, b1, W2, b2, W3, b3, out);
}

// round 15
// speedup vs baseline: 1.5535x; 1.5499x over previous
#include <cuda_runtime.h>
#include <cuda_fp16.h>
#include <math.h>

#define BTCH 2
#define NTOK 6400
#define NBINS 50
#define BINSZ 128
#define DDIM 32
#define FDIM 256
#define NKEY 100

// output packing (floats): [bins_split | x_features_binned | dm | msk_f_binned]
#define O1 12800ULL
#define O2 3289600ULL
#define O3 55718400ULL

// work-queue items: [fill 800 | compute 1600 | gather 200]
#define FILL_ITEMS  800
#define COMP_BASE   800
#define GATH_BASE   2400
#define TOTAL_ITEMS 2600

#define PERSIST_BLOCKS 444   // 148 SMs x 3 CTAs

__device__ int g_bin_idx[BTCH * NTOK];
__device__ int g_bins[BTCH * NTOK];
__device__ unsigned int g_work;

__device__ __forceinline__ float eluf(float x) {
    return fmaxf(x, 0.f) + (__expf(fminf(x, 0.f)) - 1.f);
}

// pack (a,b) to f16x2 (a in low half) and produce the f16x2 residual (lo)
__device__ __forceinline__ unsigned pksplit(float a, float b, unsigned &lo) {
    __half ha = __float2half_rn(a), hb = __float2half_rn(b);
    float ra = a - __half2float(ha);
    float rb = b - __half2float(hb);
    __half2 H = __halves2half2(ha, hb);
    __half2 L = __halves2half2(__float2half_rn(ra), __float2half_rn(rb));
    lo = *reinterpret_cast<unsigned*>(&L);
    return *reinterpret_cast<unsigned*>(&H);
}

__device__ __forceinline__ void mma16816(float& d0, float& d1, float& d2, float& d3,
                                         unsigned a0, unsigned a1, unsigned a2, unsigned a3,
                                         unsigned b0, unsigned b1) {
    asm volatile(
        "mma.sync.aligned.m16n8k16.row.col.f32.f16.f16.f32 "
        "{%0,%1,%2,%3},{%4,%5,%6,%7},{%8,%9},{%0,%1,%2,%3};"
        : "+f"(d0), "+f"(d1), "+f"(d2), "+f"(d3)
        : "r"(a0), "r"(a1), "r"(a2), "r"(a3), "r"(b0), "r"(b1));
}

// ---------------------------------------------------------------------------
// Kernel A: LSH bin assignment
// ---------------------------------------------------------------------------
__global__ void k_bins(const float* __restrict__ xd,
                       const int* __restrict__ msk,
                       const float* __restrict__ codebook)
{
    __shared__ float cb[25 * 32];
    int tid = threadIdx.x;
    for (int e = tid; e < 25 * 32; e += 128) {
        int h = e >> 5, d = e & 31;
        cb[e] = codebook[d * 100 + h];
    }
    __syncthreads();

    int gid = blockIdx.x * 128 + tid;
    const float* xr = xd + (size_t)gid * DDIM;
    float x[32];
#pragma unroll
    for (int c = 0; c < 8; c++) {
        float4 v = ((const float4*)xr)[c];
        x[c * 4 + 0] = v.x; x[c * 4 + 1] = v.y; x[c * 4 + 2] = v.z; x[c * 4 + 3] = v.w;
    }
    float mul[25];
#pragma unroll
    for (int h = 0; h < 25; h++) {
        float a0 = 0.f, a1 = 0.f, a2 = 0.f, a3 = 0.f;
#pragma unroll
        for (int d = 0; d < 32; d += 4) {
            a0 += x[d + 0] * cb[h * 32 + d + 0];
            a1 += x[d + 1] * cb[h * 32 + d + 1];
            a2 += x[d + 2] * cb[h * 32 + d + 2];
            a3 += x[d + 3] * cb[h * 32 + d + 3];
        }
        mul[h] = (a0 + a1) + (a2 + a3);
    }
    float best = -INFINITY; int arg = 0;
#pragma unroll
    for (int h = 0; h < 25; h++)
        if (mul[h] > best) { best = mul[h]; arg = h; }
#pragma unroll
    for (int h = 0; h < 25; h++) {
        float v = -mul[h];
        if (v > best) { best = v; arg = 25 + h; }
    }
    g_bin_idx[gid] = arg + (msk[gid] != 0 ? 0 : (NBINS - 1));
}

// ---------------------------------------------------------------------------
// Kernel B: parallel stable counting scatter. block = (batch, key).
// base = #(keys < key); stable rank among equal keys by ascending index.
// ---------------------------------------------------------------------------
__global__ void k_scatter(float* __restrict__ out)
{
    int bk = blockIdx.x;
    int b = bk / NKEY, key = bk % NKEY;
    int t = threadIdx.x;                 // 256 threads
    if (bk == 0 && t == 0) g_work = 0u;  // reset k_dm work queue

    const int* keys = g_bin_idx + b * NTOK;

    // pass 1: count keys < key
    int lessc = 0;
#pragma unroll 5
    for (int c = 0; c < 25; c++)
        lessc += (keys[c * 256 + t] < key);

    __shared__ int red[256];
    red[t] = lessc;
    __syncthreads();
    for (int s = 128; s > 0; s >>= 1) {
        if (t < s) red[t] += red[t + s];
        __syncthreads();
    }
    int basepos = red[0];
    __syncthreads();

    // pass 2: stable ordered scatter
    __shared__ int wcnt[8];
    int wid = t >> 5, ln = t & 31;
    int*   ob = g_bins + b * NTOK;
    float* of = out + (size_t)b * NTOK;
    int run = 0;
    for (int c = 0; c < 25; c++) {
        int idx = c * 256 + t;
        bool eq = (keys[idx] == key);
        unsigned bal = __ballot_sync(0xffffffffu, eq);
        if (ln == 0) wcnt[wid] = __popc(bal);
        __syncthreads();
        int woff = 0, tot = 0;
#pragma unroll
        for (int q = 0; q < 8; q++) {
            tot += wcnt[q];
            if (q < wid) woff += wcnt[q];
        }
        if (eq) {
            int pos = basepos + run + woff + __popc(bal & ((1u << ln) - 1u));
            ob[pos] = idx;
            of[pos] = (float)idx;
        }
        run += tot;
        __syncthreads();
    }
}

// ---------------------------------------------------------------------------
// Kernel D: persistent work-queue kernel. 444 blocks x 128 threads, 3 CTA/SM.
// fill(800): zero masked dm rows. gather(200): feature/mask copy.
// compute(1600): per (tile, ig, jg) 32x32 active pairs. Layer 1 factored
// U[i]+V[j]; layers 2+3 on tensor cores (mma.sync m16n8k16, split-fp16,
// fp32 accumulate). D-fragment of layer N is bit-identical to the A-fragment
// of layer N+1, so elu+repack stays in registers.
// ---------------------------------------------------------------------------
__global__ void __launch_bounds__(128, 3) k_dm(
    const float* __restrict__ xd, const float* __restrict__ xf,
    const int* __restrict__ msk,
    const float* __restrict__ W1, const float* __restrict__ b1,
    const float* __restrict__ W2, const float* __restrict__ b2,
    const float* __restrict__ W3, const float* __restrict__ b3,
    float* __restrict__ out)
{
    extern __shared__ float sm[];
    int*   actS = (int*)sm;          // 128
    int*   hdr  = (int*)(sm + 128);  // 16
    float* W1s  = sm + 144;          // 2048
    float* W2s  = sm + 2192;         // 1024
    float* W3s  = sm + 3216;         // 1024
    float* b2s  = sm + 4240;         // 32
    float* b3s  = sm + 4272;         // 32
    float* XdS  = sm + 4304;         // 64*36 = 2304 (rows 0-31 i, 32-63 j)
    float* US   = sm + 6608;         // 32*36 = 1152
    float* VS   = sm + 7760;         // 32*34 = 1088 (row-major V[j][k])
    // total 8848 floats = 35392 B

    int tid = threadIdx.x;
    int w = tid >> 5, lane = tid & 31;
    int g4 = lane >> 2, l4 = lane & 3;   // mma groupID / tid-in-group

    // stage weights once per CTA
    for (int e = tid; e < 2048; e += 128) W1s[e] = W1[e];
    for (int e = tid; e < 1024; e += 128) { W2s[e] = W2[e]; W3s[e] = W3[e]; }
    if (tid < 32) { b2s[tid] = b2[tid]; b3s[tid] = b3[tid]; }
    __syncthreads();

    for (;;) {
        if (tid == 0) hdr[15] = (int)atomicAdd(&g_work, 1u);
        __syncthreads();
        int item = hdr[15];
        if (item >= TOTAL_ITEMS) return;

        if (item < FILL_ITEMS) {
            // ------------- fill: zero masked dm rows, coalesced -------------
            int tile = item >> 3, sub = item & 7;   // 16 i-rows per item
            int b = tile / NBINS, bin = tile % NBINS;
            int rowt = g_bins[b * NTOK + bin * BINSZ + tid];
            actS[tid] = (msk[b * NTOK + rowt] != 0);
            __syncthreads();
            float4 z4 = make_float4(0.f, 0.f, 0.f, 0.f);
            float* tbase = out + O2 + (size_t)tile * BINSZ * BINSZ * 32;
            for (int ii = 0; ii < 16; ii++) {
                int i = sub * 16 + ii;
                float* rowp = tbase + (size_t)i * (BINSZ * 32);
                if (!actS[i]) {
                    float4* rp = (float4*)rowp;
#pragma unroll
                    for (int e = 0; e < 8; e++) rp[e * 128 + tid] = z4;
                } else {
                    for (int j = w; j < 128; j += 4)
                        if (!actS[j]) rowp[j * 32 + lane] = 0.f;
                }
            }
        } else if (item < GATH_BASE) {
            // ------------- compute: active x active pairs via mma -----------
            int cb   = item - COMP_BASE;
            int tile = cb >> 4;
            int ig   = (cb >> 2) & 3;
            int jg   = cb & 3;
            int b    = tile / NBINS;
            int bin  = tile % NBINS;
            int base = b * NTOK + bin * BINSZ;

            int rowt = g_bins[base + tid];
            int m = (msk[b * NTOK + rowt] != 0);
            unsigned bal = __ballot_sync(0xffffffffu, m);
            if (lane == 0) hdr[1 + w] = __popc(bal);
            __syncthreads();
            if (tid == 0) {
                int off = 0;
#pragma unroll
                for (int q = 0; q < 4; q++) { hdr[5 + q] = off; off += hdr[1 + q]; }
                hdr[0] = off;
            }
            __syncthreads();
            int nAct = hdr[0];
            if (ig * 32 < nAct && jg * 32 < nAct) {
                if (m) actS[hdr[5 + w] + __popc(bal & ((1u << lane) - 1u))] = tid;
                __syncthreads();

                int ni = min(32, nAct - ig * 32);
                int nj = min(32, nAct - jg * 32);

                // gather 64 x_dist rows (clamped duplicates), stride 36
#pragma unroll
                for (int c = 0; c < 4; c++) {
                    int idx = c * 128 + tid;
                    int r = idx >> 3, q = idx & 7;
                    int slot = (r < 32) ? actS[ig * 32 + min(r, ni - 1)]
                                        : actS[jg * 32 + min(r - 32, nj - 1)];
                    int trow = g_bins[base + slot];
                    float4 v = ((const float4*)(xd + ((size_t)(b * NTOK + trow)) * DDIM))[q];
                    *(float4*)(XdS + r * 36 + q * 4) = v;
                }
                __syncthreads();

                // U[i][o] (stride 36) and V[j][o] (row-major, stride 34)
                {
                    int r = tid >> 2, og = (tid & 3) * 8;
                    float acc[8];
#pragma unroll
                    for (int c = 0; c < 8; c++) acc[c] = b1[og + c];
#pragma unroll
                    for (int d = 0; d < 32; d++) {
                        float xv = XdS[r * 36 + d];
                        const float* wr = W1s + d * 32 + og;
#pragma unroll
                        for (int c = 0; c < 8; c++) acc[c] += xv * wr[c];
                    }
                    float* u = US + r * 36 + og;
#pragma unroll
                    for (int c = 0; c < 8; c++) u[c] = acc[c];

                    float av[8];
#pragma unroll
                    for (int c = 0; c < 8; c++) av[c] = 0.f;
#pragma unroll
                    for (int d = 0; d < 32; d++) {
                        float xv = XdS[(32 + r) * 36 + d];
                        const float* wr = W1s + (32 + d) * 32 + og;
#pragma unroll
                        for (int c = 0; c < 8; c++) av[c] += xv * wr[c];
                    }
                    float* vv = VS + r * 34 + og;
#pragma unroll
                    for (int c = 0; c < 8; c++) vv[c] = av[c];
                }
                __syncthreads();

                // B fragments (hi/lo) for W2, W3:  [kt*4+nt], regs b0/b1
                unsigned b2h0[8], b2h1[8], b2l0[8], b2l1[8];
                unsigned b3h0[8], b3h1[8], b3l0[8], b3l1[8];
#pragma unroll
                for (int kt = 0; kt < 2; kt++) {
#pragma unroll
                    for (int nt = 0; nt < 4; nt++) {
                        int f = kt * 4 + nt;
                        int n = nt * 8 + g4;
                        int k0 = kt * 16 + l4 * 2;
                        b2h0[f] = pksplit(W2s[k0 * 32 + n],       W2s[(k0 + 1) * 32 + n], b2l0[f]);
                        b2h1[f] = pksplit(W2s[(k0 + 8) * 32 + n], W2s[(k0 + 9) * 32 + n], b2l1[f]);
                        b3h0[f] = pksplit(W3s[k0 * 32 + n],       W3s[(k0 + 1) * 32 + n], b3l0[f]);
                        b3h1[f] = pksplit(W3s[(k0 + 8) * 32 + n], W3s[(k0 + 9) * 32 + n], b3l1[f]);
                    }
                }

                float* tbase = out + O2 + (size_t)tile * BINSZ * BINSZ * 32;

#pragma unroll 1
                for (int ii = 0; ii < 8; ii++) {
                    int li = w * 8 + ii;
                    if (li >= ni) break;
                    int s_i = actS[ig * 32 + li];
                    float* ibase = tbase + (size_t)s_i * (BINSZ * 32);

                    // U values this thread needs: k = kb + l4*2 (+1), kb in {0,8,16,24}
                    float2 u2[4];
#pragma unroll
                    for (int q = 0; q < 4; q++)
                        u2[q] = *(const float2*)(US + li * 36 + q * 8 + l4 * 2);

#pragma unroll 1
                    for (int jh = 0; jh < 2; jh++) {
                        int jl0 = jh * 16 + g4;
                        int jl1 = jl0 + 8;
                        bool ok0 = (jl0 < nj), ok1 = (jl1 < nj);
                        if (!__any_sync(0xffffffffu, ok0)) break;
                        int jc0 = min(jl0, nj - 1), jc1 = min(jl1, nj - 1);

                        float2 va[4], vb[4];
#pragma unroll
                        for (int q = 0; q < 4; q++) {
                            va[q] = *(const float2*)(VS + jc0 * 34 + q * 8 + l4 * 2);
                            vb[q] = *(const float2*)(VS + jc1 * 34 + q * 8 + l4 * 2);
                        }

                        // h1 A-fragments (hi/lo), layer-2 input
                        unsigned ah[2][4], al[2][4];
#pragma unroll
                        for (int kt = 0; kt < 2; kt++) {
#pragma unroll
                            for (int h = 0; h < 2; h++) {
                                int q = kt * 2 + h;
                                float f0 = eluf(u2[q].x + va[q].x);
                                float f1 = eluf(u2[q].y + va[q].y);
                                float g0 = eluf(u2[q].x + vb[q].x);
                                float g1 = eluf(u2[q].y + vb[q].y);
                                ah[kt][h * 2 + 0] = pksplit(f0, f1, al[kt][h * 2 + 0]);
                                ah[kt][h * 2 + 1] = pksplit(g0, g1, al[kt][h * 2 + 1]);
                            }
                        }

                        // layer 2: C init = bias, 3-combo split mma
                        float c0[4], c1[4], c2[4], c3[4];
#pragma unroll
                        for (int nt = 0; nt < 4; nt++) {
                            int col = nt * 8 + l4 * 2;
                            c0[nt] = b2s[col]; c1[nt] = b2s[col + 1];
                            c2[nt] = c0[nt];   c3[nt] = c1[nt];
                        }
#pragma unroll
                        for (int nt = 0; nt < 4; nt++) {
#pragma unroll
                            for (int kt = 0; kt < 2; kt++) {
                                int f = kt * 4 + nt;
                                mma16816(c0[nt], c1[nt], c2[nt], c3[nt],
                                         ah[kt][0], ah[kt][1], ah[kt][2], ah[kt][3],
                                         b2h0[f], b2h1[f]);
                                mma16816(c0[nt], c1[nt], c2[nt], c3[nt],
                                         al[kt][0], al[kt][1], al[kt][2], al[kt][3],
                                         b2h0[f], b2h1[f]);
                                mma16816(c0[nt], c1[nt], c2[nt], c3[nt],
                                         ah[kt][0], ah[kt][1], ah[kt][2], ah[kt][3],
                                         b2l0[f], b2l1[f]);
                            }
                        }

                        // h2 = elu(C); D fragment == next A fragment layout
#pragma unroll
                        for (int kt = 0; kt < 2; kt++) {
                            int n0 = kt * 2, n1 = kt * 2 + 1;
                            ah[kt][0] = pksplit(eluf(c0[n0]), eluf(c1[n0]), al[kt][0]);
                            ah[kt][1] = pksplit(eluf(c2[n0]), eluf(c3[n0]), al[kt][1]);
                            ah[kt][2] = pksplit(eluf(c0[n1]), eluf(c1[n1]), al[kt][2]);
                            ah[kt][3] = pksplit(eluf(c2[n1]), eluf(c3[n1]), al[kt][3]);
                        }

                        // layer 3
#pragma unroll
                        for (int nt = 0; nt < 4; nt++) {
                            int col = nt * 8 + l4 * 2;
                            c0[nt] = b3s[col]; c1[nt] = b3s[col + 1];
                            c2[nt] = c0[nt];   c3[nt] = c1[nt];
                        }
#pragma unroll
                        for (int nt = 0; nt < 4; nt++) {
#pragma unroll
                            for (int kt = 0; kt < 2; kt++) {
                                int f = kt * 4 + nt;
                                mma16816(c0[nt], c1[nt], c2[nt], c3[nt],
                                         ah[kt][0], ah[kt][1], ah[kt][2], ah[kt][3],
                                         b3h0[f], b3h1[f]);
                                mma16816(c0[nt], c1[nt], c2[nt], c3[nt],
                                         al[kt][0], al[kt][1], al[kt][2], al[kt][3],
                                         b3h0[f], b3h1[f]);
                                mma16816(c0[nt], c1[nt], c2[nt], c3[nt],
                                         ah[kt][0], ah[kt][1], ah[kt][2], ah[kt][3],
                                         b3l0[f], b3l1[f]);
                            }
                        }

                        // final elu + store (8B vector stores, rows = j slots)
                        int sj0 = actS[jg * 32 + jc0];
                        int sj1 = actS[jg * 32 + jc1];
#pragma unroll
                        for (int nt = 0; nt < 4; nt++) {
                            int col = nt * 8 + l4 * 2;
                            if (ok0) {
                                float2 v; v.x = eluf(c0[nt]); v.y = eluf(c1[nt]);
                                *(float2*)(ibase + (size_t)sj0 * 32 + col) = v;
                            }
                            if (ok1) {
                                float2 v; v.x = eluf(c2[nt]); v.y = eluf(c3[nt]);
                                *(float2*)(ibase + (size_t)sj1 * 32 + col) = v;
                            }
                        }
                    }
                }
            }
        } else {
            // ------------- gather: x_features_binned + msk_f_binned ---------
            int g = item - GATH_BASE;            // 0..199, 64 rows each
            if (tid < 64) {
                int gid = g * 64 + tid;
                int bb = gid / NTOK;
                int src = g_bins[gid];
                out[O3 + gid] = (msk[bb * NTOK + src] != 0) ? 1.f : 0.f;
            }
            int base = g * 64;
            float4* dst = (float4*)(out + O1);
#pragma unroll 4
            for (int p = 0; p < 32; p++) {
                int idx = p * 128 + tid;
                int r = idx >> 6, c = idx & 63;
                int gid = base + r;
                int bb = gid / NTOK;
                int src = g_bins[gid];
                dst[(size_t)gid * 64 + c] =
                    ((const float4*)(xf + ((size_t)(bb * NTOK + src)) * FDIM))[c];
            }
        }
        __syncthreads();   // smem reuse fence before next item
    }
}

// ---------------------------------------------------------------------------
extern "C" void kernel_launch(void* const* d_in, const int* in_sizes, int n_in,
                              void* d_out, int out_size)
{
    const float* xd  = (const float*)d_in[0];
    const float* xf  = (const float*)d_in[1];
    const int*   mk  = (const int*)d_in[2];
    const float* cb  = (const float*)d_in[3];
    const float* W1  = (const float*)d_in[4];
    const float* b1  = (const float*)d_in[5];
    const float* W2  = (const float*)d_in[6];
    const float* b2  = (const float*)d_in[7];
    const float* W3  = (const float*)d_in[8];
    const float* b3  = (const float*)d_in[9];
    float* out = (float*)d_out;

    k_bins<<<100, 128>>>(xd, mk, cb);
    k_scatter<<<BTCH * NKEY, 256>>>(out);

    cudaFuncSetAttribute(k_dm, cudaFuncAttributeMaxDynamicSharedMemorySize, 35392);
    k_dm<<<PERSIST_BLOCKS, 128, 35392>>>(
        xd, xf, mk, W1, b1, W2, b2, W3, b3, out);
}